// round 9
// baseline (speedup 1.0000x reference)
#include <cuda_runtime.h>
#include <cuda_fp16.h>
#include <cstdint>
#include <math.h>

// Problem constants
#define NTOK 8192
#define DDIM 1024
#define DFF  4096
#define NEXP 8
#define NPAD 9216      // 8192 + 8*128 headroom, multiple of 128
#define MTMAX 72       // max total M-tiles across experts (9216/128)

// ---------------------------------------------------------------------------
// Scratch (device globals; no dynamic allocation allowed)
// g_Wh shared by both GEMMs (stream-ordered overwrite between phases).
// ---------------------------------------------------------------------------
__device__ int    g_expert_id[NTOK];
__device__ int    g_counts[NEXP];
__device__ int    g_cursor[NEXP];
__device__ int    g_tile_off[NEXP + 1];
__device__ int    g_perm[NPAD];
__device__ __half g_xh[(size_t)NPAD * DDIM];          // permuted tokens, fp16
__device__ __half g_h[(size_t)NPAD * DFF];            // hidden activations, fp16
__device__ __half g_Wh[(size_t)NEXP * DFF * DDIM];    // W1^T then W2^T, K-major

// ---------------------------------------------------------------------------
// helpers
// ---------------------------------------------------------------------------
__device__ __forceinline__ uint32_t smem_u32(const void* p) {
    uint32_t a;
    asm("{ .reg .u64 t; cvta.to.shared.u64 t, %1; cvt.u32.u64 %0, t; }"
        : "=r"(a) : "l"(p));
    return a;
}

__device__ __forceinline__ void ldsm4(uint32_t* r, uint32_t addr) {
    asm volatile("ldmatrix.sync.aligned.m8n8.x4.shared.b16 {%0,%1,%2,%3}, [%4];"
                 : "=r"(r[0]), "=r"(r[1]), "=r"(r[2]), "=r"(r[3]) : "r"(addr));
}

__device__ __forceinline__ void mma16816(float* c, const uint32_t* a,
                                         uint32_t b0, uint32_t b1) {
    asm volatile(
        "mma.sync.aligned.m16n8k16.row.col.f32.f16.f16.f32 "
        "{%0,%1,%2,%3},{%4,%5,%6,%7},{%8,%9},{%0,%1,%2,%3};"
        : "+f"(c[0]), "+f"(c[1]), "+f"(c[2]), "+f"(c[3])
        : "r"(a[0]), "r"(a[1]), "r"(a[2]), "r"(a[3]), "r"(b0), "r"(b1));
}

__device__ __forceinline__ void cp16(uint32_t saddr, const void* g) {
    asm volatile("cp.async.cg.shared.global [%0], [%1], 16;"
                 :: "r"(saddr), "l"(g) : "memory");
}
#define CP_COMMIT() asm volatile("cp.async.commit_group;" ::: "memory")
#define CP_WAIT1()  asm volatile("cp.async.wait_group 1;" ::: "memory")

// ---------------------------------------------------------------------------
// 1) init
// ---------------------------------------------------------------------------
__global__ void init_kernel() {
    int idx = blockIdx.x * blockDim.x + threadIdx.x;
    if (idx < NPAD) g_perm[idx] = -1;
    if (idx < NEXP) g_counts[idx] = 0;
}

// ---------------------------------------------------------------------------
// 2) gating: fp32 logits + strict-first argmax + histogram (warp per token)
// ---------------------------------------------------------------------------
__global__ __launch_bounds__(256) void gate_kernel(const float* __restrict__ x,
                                                   const float* __restrict__ gW,
                                                   const float* __restrict__ gb) {
    int tok  = (blockIdx.x * 256 + threadIdx.x) >> 5;
    int lane = threadIdx.x & 31;
    if (tok >= NTOK) return;
    const float* xr = x + (size_t)tok * DDIM;
    float acc[8];
#pragma unroll
    for (int j = 0; j < 8; j++) acc[j] = 0.f;
#pragma unroll 8
    for (int i = 0; i < 32; i++) {
        int d = lane + i * 32;
        float xv = xr[d];
        float4 w0 = *reinterpret_cast<const float4*>(gW + (size_t)d * 8);
        float4 w1 = *reinterpret_cast<const float4*>(gW + (size_t)d * 8 + 4);
        acc[0] += xv * w0.x; acc[1] += xv * w0.y; acc[2] += xv * w0.z; acc[3] += xv * w0.w;
        acc[4] += xv * w1.x; acc[5] += xv * w1.y; acc[6] += xv * w1.z; acc[7] += xv * w1.w;
    }
#pragma unroll
    for (int j = 0; j < 8; j++) {
#pragma unroll
        for (int o = 16; o; o >>= 1) acc[j] += __shfl_xor_sync(0xffffffffu, acc[j], o);
    }
    if (lane == 0) {
        float best = acc[0] + gb[0];
        int bi = 0;
#pragma unroll
        for (int j = 1; j < 8; j++) {
            float v = acc[j] + gb[j];
            if (v > best) { best = v; bi = j; }   // strict > : first-max, matches argmax
        }
        g_expert_id[tok] = bi;
        atomicAdd(&g_counts[bi], 1);
    }
}

// ---------------------------------------------------------------------------
// 3) scan
// ---------------------------------------------------------------------------
__global__ void scan_kernel() {
    int off = 0, toff = 0;
    for (int e = 0; e < NEXP; e++) {
        int c = g_counts[e];
        int pad = (c + 127) & ~127;
        g_cursor[e]   = off;
        g_tile_off[e] = toff;
        off  += pad;
        toff += pad >> 7;
    }
    g_tile_off[NEXP] = toff;
}

// ---------------------------------------------------------------------------
// 4) gather: warp per token — permute + fp32->fp16
// ---------------------------------------------------------------------------
__global__ __launch_bounds__(256) void gather_kernel(const float* __restrict__ x) {
    int tok  = (blockIdx.x * 256 + threadIdx.x) >> 5;
    int lane = threadIdx.x & 31;
    if (tok >= NTOK) return;
    int e = g_expert_id[tok];
    int slot = 0;
    if (lane == 0) slot = atomicAdd(&g_cursor[e], 1);
    slot = __shfl_sync(0xffffffffu, slot, 0);
    if (lane == 0) g_perm[slot] = tok;
    const float4* xr = reinterpret_cast<const float4*>(x + (size_t)tok * DDIM);
    __half* dst = g_xh + (size_t)slot * DDIM;
#pragma unroll
    for (int i = 0; i < 8; i++) {
        float4 v = xr[lane + i * 32];
        __half hv[4] = { __float2half_rn(v.x), __float2half_rn(v.y),
                         __float2half_rn(v.z), __float2half_rn(v.w) };
        *reinterpret_cast<uint2*>(dst + lane * 4 + i * 128) =
            *reinterpret_cast<const uint2*>(hv);
    }
}

// ---------------------------------------------------------------------------
// 5) weight conversion: fp32 [rows][cols] -> fp16 transposed [cols][rows]
//    64(r) x 32(c) tiles; half2 stores give full 128B sectors on output.
// ---------------------------------------------------------------------------
__device__ __forceinline__ void transpose_cvt_body(const float* __restrict__ in,
                                                   __half* __restrict__ out,
                                                   int rows, int cols) {
    __shared__ float tile[32][66];   // [c][r] layout, 64 r + 2 pad
    size_t mat = (size_t)rows * cols;
    in  += (size_t)blockIdx.z * mat;
    out += (size_t)blockIdx.z * mat;
    int c0 = blockIdx.x * 32, r0 = blockIdx.y * 64;
    int tx = threadIdx.x, ty = threadIdx.y;
    // load 64 rows x 32 cols, coalesced on cols; write transposed into tile
#pragma unroll
    for (int i = 0; i < 64; i += 8)
        tile[tx][ty + i] = in[(size_t)(r0 + ty + i) * cols + (c0 + tx)];
    __syncthreads();
    // store: each thread writes half2 (2 consecutive r) -> 128B per c-row
#pragma unroll
    for (int i = 0; i < 32; i += 8) {
        int c = ty + i;
        float v0 = tile[c][tx * 2];
        float v1 = tile[c][tx * 2 + 1];
        *reinterpret_cast<__half2*>(out + (size_t)(c0 + c) * rows + (r0 + tx * 2)) =
            __floats2half2_rn(v0, v1);
    }
}

__global__ void transpose_cvt_W1(const float* __restrict__ in) {
    transpose_cvt_body(in, g_Wh, DDIM, DFF);   // W1[e]: [D][DFF] -> [DFF][D]
}
__global__ void transpose_cvt_W2(const float* __restrict__ in) {
    transpose_cvt_body(in, g_Wh, DFF, DDIM);   // W2[e]: [DFF][D] -> [D][DFF]
}

// ---------------------------------------------------------------------------
// 6/7) mma.sync GEMM: 128x256 CTA tile, warp tile 64x64 (2M x 4N warps),
//      K-chunk 32, 2-stage cp.async, 80B smem rows (ldmatrix conflict-free)
//   PH1: h = gelu(xh @ W1h^T + b1)  -> fp16
//   PH2: out[perm] = h @ W2h^T + b2 -> fp32 scatter
// ---------------------------------------------------------------------------
static constexpr int ROWB    = 80;             // 64B data + 16B pad
static constexpr int A_TILEB = 128 * ROWB;     // 10240
static constexpr int B_TILEB = 256 * ROWB;     // 20480
static constexpr int STAGEB  = A_TILEB + B_TILEB;      // 30720
static constexpr int GEMM_SMEM = 2 * STAGEB;           // 61440 (dynamic)

template <int KDIM, bool PH1>
__global__ __launch_bounds__(256, 1)
void moe_gemm_kernel(const float* __restrict__ bias, float* __restrict__ outp) {
    extern __shared__ __align__(128) uint8_t smem[];

    const int mt = blockIdx.x;
    if (mt >= g_tile_off[NEXP]) return;
    int e = 0;
#pragma unroll
    for (int i = 1; i < NEXP; i++)
        if (g_tile_off[i] <= mt) e = i;

    const int nt   = blockIdx.y;
    const int row0 = mt * 128;
    const int tid  = threadIdx.x;
    const int wid  = tid >> 5;
    const int lane = tid & 31;
    const int wm   = wid >> 2;     // warp M index (2)
    const int wn   = wid & 3;      // warp N index (4)
    const uint32_t sbase = smem_u32(smem);

    const __half* Ab = (PH1 ? g_xh : g_h) + (size_t)row0 * KDIM;
    const __half* Bb = g_Wh
                       + (size_t)e * (size_t)(PH1 ? DFF : DDIM) * KDIM
                       + (size_t)nt * 256 * KDIM;

    auto load_chunk = [&](int kc, int stage) {
        uint32_t sa = sbase + stage * STAGEB;
        uint32_t sb = sa + A_TILEB;
        // A: 512 16B-chunks (128 rows x 4)
#pragma unroll
        for (int j = 0; j < 2; j++) {
            int i = tid + j * 256;
            int r = i >> 2, cc = i & 3;
            cp16(sa + r * ROWB + cc * 16, Ab + (size_t)r * KDIM + kc * 32 + cc * 8);
        }
        // B: 1024 16B-chunks (256 rows x 4)
#pragma unroll
        for (int j = 0; j < 4; j++) {
            int i = tid + j * 256;
            int r = i >> 2, cc = i & 3;
            cp16(sb + r * ROWB + cc * 16, Bb + (size_t)r * KDIM + kc * 32 + cc * 8);
        }
    };

    float c[4][8][4];
#pragma unroll
    for (int mi = 0; mi < 4; mi++)
#pragma unroll
        for (int nj = 0; nj < 8; nj++)
#pragma unroll
            for (int q = 0; q < 4; q++) c[mi][nj][q] = 0.f;

    const int lrow  = lane & 15;
    const int lhalf = (lane >> 4) & 1;
    constexpr int NK = KDIM / 32;

    load_chunk(0, 0);
    CP_COMMIT();

    for (int kc = 0; kc < NK; kc++) {
        int nk = (kc + 1 < NK) ? kc + 1 : kc;      // last iter: harmless reload
        load_chunk(nk, (kc + 1) & 1);
        CP_COMMIT();
        CP_WAIT1();
        __syncthreads();

        uint32_t As = sbase + (kc & 1) * STAGEB;
        uint32_t Bs = As + A_TILEB;
#pragma unroll
        for (int ks = 0; ks < 2; ks++) {
            const int bytecol = ks * 32 + lhalf * 16;
            uint32_t a[4][4], b[4][4];
#pragma unroll
            for (int mi = 0; mi < 4; mi++)
                ldsm4(a[mi], As + (wm * 64 + mi * 16 + lrow) * ROWB + bytecol);
#pragma unroll
            for (int nb = 0; nb < 4; nb++)
                ldsm4(b[nb], Bs + (wn * 64 + nb * 16 + lrow) * ROWB + bytecol);
#pragma unroll
            for (int mi = 0; mi < 4; mi++)
#pragma unroll
                for (int nb = 0; nb < 4; nb++) {
                    mma16816(c[mi][2 * nb + 0], a[mi], b[nb][0], b[nb][2]);
                    mma16816(c[mi][2 * nb + 1], a[mi], b[nb][1], b[nb][3]);
                }
        }
        __syncthreads();
    }

    // -------- epilogue from register accumulators --------
    const int g4 = lane >> 2, t4 = lane & 3;
#pragma unroll
    for (int mi = 0; mi < 4; mi++) {
        const int rA = row0 + wm * 64 + mi * 16 + g4;     // rows for c0,c1
        const int rB = rA + 8;                            // rows for c2,c3
        if constexpr (PH1) {
            const float* be = bias + (size_t)e * DFF;
            __half* hA = g_h + (size_t)rA * DFF;
            __half* hB = g_h + (size_t)rB * DFF;
#pragma unroll
            for (int nj = 0; nj < 8; nj++) {
                const int col = nt * 256 + wn * 64 + nj * 8 + t4 * 2;
                float b0 = be[col], b1 = be[col + 1];
                float v0 = c[mi][nj][0] + b0;
                float v1 = c[mi][nj][1] + b1;
                float v2 = c[mi][nj][2] + b0;
                float v3 = c[mi][nj][3] + b1;
                v0 = 0.5f * v0 * (1.0f + erff(v0 * 0.70710678118654752440f));
                v1 = 0.5f * v1 * (1.0f + erff(v1 * 0.70710678118654752440f));
                v2 = 0.5f * v2 * (1.0f + erff(v2 * 0.70710678118654752440f));
                v3 = 0.5f * v3 * (1.0f + erff(v3 * 0.70710678118654752440f));
                *reinterpret_cast<__half2*>(hA + col) = __floats2half2_rn(v0, v1);
                *reinterpret_cast<__half2*>(hB + col) = __floats2half2_rn(v2, v3);
            }
        } else {
            const float* be = bias + (size_t)e * DDIM;
            const int tokA = g_perm[rA];
            const int tokB = g_perm[rB];
#pragma unroll
            for (int nj = 0; nj < 8; nj++) {
                const int col = nt * 256 + wn * 64 + nj * 8 + t4 * 2;
                float b0 = be[col], b1 = be[col + 1];
                if (tokA >= 0) {
                    float2 v = { c[mi][nj][0] + b0, c[mi][nj][1] + b1 };
                    *reinterpret_cast<float2*>(outp + (size_t)tokA * DDIM + col) = v;
                }
                if (tokB >= 0) {
                    float2 v = { c[mi][nj][2] + b0, c[mi][nj][3] + b1 };
                    *reinterpret_cast<float2*>(outp + (size_t)tokB * DDIM + col) = v;
                }
            }
        }
    }
}

// ---------------------------------------------------------------------------
// Launch: convert W1 -> GEMM1 -> convert W2 (overwrite) -> GEMM2
// ---------------------------------------------------------------------------
extern "C" void kernel_launch(void* const* d_in, const int* in_sizes, int n_in,
                              void* d_out, int out_size) {
    const float* x  = (const float*)d_in[0];
    const float* gW = (const float*)d_in[1];
    const float* gb = (const float*)d_in[2];
    const float* W1 = (const float*)d_in[3];
    const float* b1 = (const float*)d_in[4];
    const float* W2 = (const float*)d_in[5];
    const float* b2 = (const float*)d_in[6];
    float* out = (float*)d_out;

    // opt into >48KB dynamic smem (attribute set, not an allocation)
    static bool attr_done = false;
    if (!attr_done) {
        cudaFuncSetAttribute(moe_gemm_kernel<DDIM, true>,
                             cudaFuncAttributeMaxDynamicSharedMemorySize, GEMM_SMEM);
        cudaFuncSetAttribute(moe_gemm_kernel<DFF, false>,
                             cudaFuncAttributeMaxDynamicSharedMemorySize, GEMM_SMEM);
        attr_done = true;
    }

    init_kernel<<<NPAD / 256, 256>>>();
    gate_kernel<<<NTOK / 8, 256>>>(x, gW, gb);
    scan_kernel<<<1, 1>>>();
    gather_kernel<<<NTOK / 8, 256>>>(x);

    transpose_cvt_W1<<<dim3(DFF / 32, DDIM / 64, NEXP), dim3(32, 8)>>>(W1);
    moe_gemm_kernel<DDIM, true ><<<dim3(MTMAX, DFF / 256), 256, GEMM_SMEM>>>(b1, nullptr);

    transpose_cvt_W2<<<dim3(DDIM / 32, DFF / 64, NEXP), dim3(32, 8)>>>(W2);
    moe_gemm_kernel<DFF,  false><<<dim3(MTMAX, DDIM / 256), 256, GEMM_SMEM>>>(b2, out);
}

// round 12
// speedup vs baseline: 1.0601x; 1.0601x over previous
#include <cuda_runtime.h>
#include <cuda_fp16.h>
#include <cstdint>
#include <math.h>

// Problem constants
#define NTOK 8192
#define DDIM 1024
#define DFF  4096
#define NEXP 8
#define NPAD 9216      // 8192 + 8*128 headroom, multiple of 128
#define MTMAX 72       // max total M-tiles across experts (9216/128)

// ---------------------------------------------------------------------------
// Scratch (device globals; no dynamic allocation allowed)
// g_Wh shared by both GEMMs (stream-ordered overwrite between phases).
// ---------------------------------------------------------------------------
__device__ int    g_expert_id[NTOK];
__device__ int    g_counts[NEXP];
__device__ int    g_cursor[NEXP];
__device__ int    g_tile_off[NEXP + 1];
__device__ int    g_perm[NPAD];
__device__ __half g_xh[(size_t)NPAD * DDIM];          // permuted tokens, fp16
__device__ __half g_h[(size_t)NPAD * DFF];            // hidden activations, fp16
__device__ __half g_Wh[(size_t)NEXP * DFF * DDIM];    // W1^T then W2^T, K-major

// ---------------------------------------------------------------------------
// helpers
// ---------------------------------------------------------------------------
__device__ __forceinline__ uint32_t smem_u32(const void* p) {
    uint32_t a;
    asm("{ .reg .u64 t; cvta.to.shared.u64 t, %1; cvt.u32.u64 %0, t; }"
        : "=r"(a) : "l"(p));
    return a;
}

__device__ __forceinline__ void ldsm4(uint32_t* r, uint32_t addr) {
    asm volatile("ldmatrix.sync.aligned.m8n8.x4.shared.b16 {%0,%1,%2,%3}, [%4];"
                 : "=r"(r[0]), "=r"(r[1]), "=r"(r[2]), "=r"(r[3]) : "r"(addr));
}

__device__ __forceinline__ void mma16816(float* c, const uint32_t* a,
                                         uint32_t b0, uint32_t b1) {
    asm volatile(
        "mma.sync.aligned.m16n8k16.row.col.f32.f16.f16.f32 "
        "{%0,%1,%2,%3},{%4,%5,%6,%7},{%8,%9},{%0,%1,%2,%3};"
        : "+f"(c[0]), "+f"(c[1]), "+f"(c[2]), "+f"(c[3])
        : "r"(a[0]), "r"(a[1]), "r"(a[2]), "r"(a[3]), "r"(b0), "r"(b1));
}

__device__ __forceinline__ void cp16(uint32_t saddr, const void* g) {
    asm volatile("cp.async.cg.shared.global [%0], [%1], 16;"
                 :: "r"(saddr), "l"(g) : "memory");
}
#define CP_COMMIT() asm volatile("cp.async.commit_group;" ::: "memory")
#define CP_WAIT1()  asm volatile("cp.async.wait_group 1;" ::: "memory")

// ---------------------------------------------------------------------------
// 1) init
// ---------------------------------------------------------------------------
__global__ void init_kernel() {
    int idx = blockIdx.x * blockDim.x + threadIdx.x;
    if (idx < NPAD) g_perm[idx] = -1;
    if (idx < NEXP) g_counts[idx] = 0;
}

// ---------------------------------------------------------------------------
// 2) gating: fp32 logits + strict-first argmax + histogram (warp per token)
// ---------------------------------------------------------------------------
__global__ __launch_bounds__(256) void gate_kernel(const float* __restrict__ x,
                                                   const float* __restrict__ gW,
                                                   const float* __restrict__ gb) {
    int tok  = (blockIdx.x * 256 + threadIdx.x) >> 5;
    int lane = threadIdx.x & 31;
    if (tok >= NTOK) return;
    const float* xr = x + (size_t)tok * DDIM;
    float acc[8];
#pragma unroll
    for (int j = 0; j < 8; j++) acc[j] = 0.f;
#pragma unroll 8
    for (int i = 0; i < 32; i++) {
        int d = lane + i * 32;
        float xv = xr[d];
        float4 w0 = *reinterpret_cast<const float4*>(gW + (size_t)d * 8);
        float4 w1 = *reinterpret_cast<const float4*>(gW + (size_t)d * 8 + 4);
        acc[0] += xv * w0.x; acc[1] += xv * w0.y; acc[2] += xv * w0.z; acc[3] += xv * w0.w;
        acc[4] += xv * w1.x; acc[5] += xv * w1.y; acc[6] += xv * w1.z; acc[7] += xv * w1.w;
    }
#pragma unroll
    for (int j = 0; j < 8; j++) {
#pragma unroll
        for (int o = 16; o; o >>= 1) acc[j] += __shfl_xor_sync(0xffffffffu, acc[j], o);
    }
    if (lane == 0) {
        float best = acc[0] + gb[0];
        int bi = 0;
#pragma unroll
        for (int j = 1; j < 8; j++) {
            float v = acc[j] + gb[j];
            if (v > best) { best = v; bi = j; }   // strict > : first-max, matches argmax
        }
        g_expert_id[tok] = bi;
        atomicAdd(&g_counts[bi], 1);
    }
}

// ---------------------------------------------------------------------------
// 3) scan
// ---------------------------------------------------------------------------
__global__ void scan_kernel() {
    int off = 0, toff = 0;
    for (int e = 0; e < NEXP; e++) {
        int c = g_counts[e];
        int pad = (c + 127) & ~127;
        g_cursor[e]   = off;
        g_tile_off[e] = toff;
        off  += pad;
        toff += pad >> 7;
    }
    g_tile_off[NEXP] = toff;
}

// ---------------------------------------------------------------------------
// 4) gather: warp per token — permute + fp32->fp16
// ---------------------------------------------------------------------------
__global__ __launch_bounds__(256) void gather_kernel(const float* __restrict__ x) {
    int tok  = (blockIdx.x * 256 + threadIdx.x) >> 5;
    int lane = threadIdx.x & 31;
    if (tok >= NTOK) return;
    int e = g_expert_id[tok];
    int slot = 0;
    if (lane == 0) slot = atomicAdd(&g_cursor[e], 1);
    slot = __shfl_sync(0xffffffffu, slot, 0);
    if (lane == 0) g_perm[slot] = tok;
    const float4* xr = reinterpret_cast<const float4*>(x + (size_t)tok * DDIM);
    __half* dst = g_xh + (size_t)slot * DDIM;
#pragma unroll
    for (int i = 0; i < 8; i++) {
        float4 v = xr[lane + i * 32];
        __half hv[4] = { __float2half_rn(v.x), __float2half_rn(v.y),
                         __float2half_rn(v.z), __float2half_rn(v.w) };
        *reinterpret_cast<uint2*>(dst + lane * 4 + i * 128) =
            *reinterpret_cast<const uint2*>(hv);
    }
}

// ---------------------------------------------------------------------------
// 5) weight conversion: fp32 [rows][cols] -> fp16 transposed [cols][rows]
//    64(r) x 32(c) tiles; half2 stores give full 128B sectors on output.
// ---------------------------------------------------------------------------
__device__ __forceinline__ void transpose_cvt_body(const float* __restrict__ in,
                                                   __half* __restrict__ out,
                                                   int rows, int cols) {
    __shared__ float tile[32][66];   // [c][r] layout, 64 r + 2 pad
    size_t mat = (size_t)rows * cols;
    in  += (size_t)blockIdx.z * mat;
    out += (size_t)blockIdx.z * mat;
    int c0 = blockIdx.x * 32, r0 = blockIdx.y * 64;
    int tx = threadIdx.x, ty = threadIdx.y;
#pragma unroll
    for (int i = 0; i < 64; i += 8)
        tile[tx][ty + i] = in[(size_t)(r0 + ty + i) * cols + (c0 + tx)];
    __syncthreads();
#pragma unroll
    for (int i = 0; i < 32; i += 8) {
        int c = ty + i;
        float v0 = tile[c][tx * 2];
        float v1 = tile[c][tx * 2 + 1];
        *reinterpret_cast<__half2*>(out + (size_t)(c0 + c) * rows + (r0 + tx * 2)) =
            __floats2half2_rn(v0, v1);
    }
}

__global__ void transpose_cvt_W1(const float* __restrict__ in) {
    transpose_cvt_body(in, g_Wh, DDIM, DFF);   // W1[e]: [D][DFF] -> [DFF][D]
}
__global__ void transpose_cvt_W2(const float* __restrict__ in) {
    transpose_cvt_body(in, g_Wh, DFF, DDIM);   // W2[e]: [DFF][D] -> [D][DFF]
}

// ---------------------------------------------------------------------------
// 6/7) mma.sync GEMM: 128x128 CTA tile, warp tile 32x64, K-chunk 32,
//      THREE-stage cp.async pipeline, ONE __syncthreads per K-iter,
//      80B smem rows (ldmatrix conflict-free)
//   PH1: h = gelu(xh @ W1h^T + b1)  -> fp16
//   PH2: out[perm] = h @ W2h^T + b2 -> fp32 scatter
// ---------------------------------------------------------------------------
static constexpr int ROWB   = 80;            // 64B data + 16B pad
static constexpr int TILEB  = 128 * ROWB;    // 10240 B per operand tile
static constexpr int STAGEB = 2 * TILEB;     // A + B per stage = 20480
static constexpr int NSTAGE = 3;
static constexpr int GEMM_SMEM = NSTAGE * STAGEB;   // 61440 (dynamic)

template <int KDIM, bool PH1>
__global__ __launch_bounds__(256, 2)
void moe_gemm_kernel(const float* __restrict__ bias, float* __restrict__ outp) {
    extern __shared__ __align__(128) uint8_t smem[];

    const int mt = blockIdx.x;
    if (mt >= g_tile_off[NEXP]) return;
    int e = 0;
#pragma unroll
    for (int i = 1; i < NEXP; i++)
        if (g_tile_off[i] <= mt) e = i;

    const int nt   = blockIdx.y;
    const int row0 = mt * 128;
    const int tid  = threadIdx.x;
    const int wid  = tid >> 5;
    const int lane = tid & 31;
    const int wm   = wid & 3;      // warp M index (4)
    const int wn   = wid >> 2;     // warp N index (2)
    const uint32_t sbase = smem_u32(smem);

    const __half* Ab = (PH1 ? g_xh : g_h) + (size_t)row0 * KDIM;
    const __half* Bb = g_Wh
                       + (size_t)e * (size_t)(PH1 ? DFF : DDIM) * KDIM
                       + (size_t)nt * 128 * KDIM;

    // per-thread load slots: 2 x (A 16B + B 16B) per chunk
    const int lr0 = tid >> 2,           lc0 = tid & 3;
    const int lr1 = (tid + 256) >> 2,   lc1 = (tid + 256) & 3;

    auto load_chunk = [&](int kc, int stage) {
        uint32_t sa = sbase + stage * STAGEB;
        uint32_t sb = sa + TILEB;
        cp16(sa + lr0 * ROWB + lc0 * 16, Ab + (size_t)lr0 * KDIM + kc * 32 + lc0 * 8);
        cp16(sb + lr0 * ROWB + lc0 * 16, Bb + (size_t)lr0 * KDIM + kc * 32 + lc0 * 8);
        cp16(sa + lr1 * ROWB + lc1 * 16, Ab + (size_t)lr1 * KDIM + kc * 32 + lc1 * 8);
        cp16(sb + lr1 * ROWB + lc1 * 16, Bb + (size_t)lr1 * KDIM + kc * 32 + lc1 * 8);
    };

    float c[2][8][4];
#pragma unroll
    for (int mi = 0; mi < 2; mi++)
#pragma unroll
        for (int nj = 0; nj < 8; nj++)
#pragma unroll
            for (int q = 0; q < 4; q++) c[mi][nj][q] = 0.f;

    const int lrow  = lane & 15;
    const int lhalf = (lane >> 4) & 1;
    constexpr int NK = KDIM / 32;

    // prologue: two stages in flight
    load_chunk(0, 0);
    CP_COMMIT();
    load_chunk(1, 1);
    CP_COMMIT();

    int stage = 0;
    for (int kc = 0; kc < NK; kc++) {
        CP_WAIT1();            // group kc complete (<=1 newer outstanding)
        __syncthreads();       // all threads see stage kc%3; prev compute done

        // prefetch stage kc+2 into the slot compute(kc-1) just vacated
        int pf = kc + 2;
        if (pf < NK) load_chunk(pf, pf >= NSTAGE ? pf - (pf / NSTAGE) * NSTAGE : pf);
        CP_COMMIT();

        uint32_t As = sbase + stage * STAGEB;
        uint32_t Bs = As + TILEB;
#pragma unroll
        for (int ks = 0; ks < 2; ks++) {
            const int bytecol = ks * 32 + lhalf * 16;
            uint32_t a[2][4], b[4][4];
#pragma unroll
            for (int mi = 0; mi < 2; mi++)
                ldsm4(a[mi], As + (wm * 32 + mi * 16 + lrow) * ROWB + bytecol);
#pragma unroll
            for (int nb = 0; nb < 4; nb++)
                ldsm4(b[nb], Bs + (wn * 64 + nb * 16 + lrow) * ROWB + bytecol);
#pragma unroll
            for (int mi = 0; mi < 2; mi++)
#pragma unroll
                for (int nb = 0; nb < 4; nb++) {
                    mma16816(c[mi][2 * nb + 0], a[mi], b[nb][0], b[nb][2]);
                    mma16816(c[mi][2 * nb + 1], a[mi], b[nb][1], b[nb][3]);
                }
        }
        stage = (stage + 1 == NSTAGE) ? 0 : stage + 1;
    }

    // -------- epilogue from register accumulators --------
    const int g4 = lane >> 2, t4 = lane & 3;
#pragma unroll
    for (int mi = 0; mi < 2; mi++) {
        const int rA = row0 + wm * 32 + mi * 16 + g4;     // rows for c0,c1
        const int rB = rA + 8;                            // rows for c2,c3
        if constexpr (PH1) {
            const float* be = bias + (size_t)e * DFF;
            __half* hA = g_h + (size_t)rA * DFF;
            __half* hB = g_h + (size_t)rB * DFF;
#pragma unroll
            for (int nj = 0; nj < 8; nj++) {
                const int col = nt * 128 + wn * 64 + nj * 8 + t4 * 2;
                float b0 = be[col], b1 = be[col + 1];
                float v0 = c[mi][nj][0] + b0;
                float v1 = c[mi][nj][1] + b1;
                float v2 = c[mi][nj][2] + b0;
                float v3 = c[mi][nj][3] + b1;
                v0 = 0.5f * v0 * (1.0f + erff(v0 * 0.70710678118654752440f));
                v1 = 0.5f * v1 * (1.0f + erff(v1 * 0.70710678118654752440f));
                v2 = 0.5f * v2 * (1.0f + erff(v2 * 0.70710678118654752440f));
                v3 = 0.5f * v3 * (1.0f + erff(v3 * 0.70710678118654752440f));
                *reinterpret_cast<__half2*>(hA + col) = __floats2half2_rn(v0, v1);
                *reinterpret_cast<__half2*>(hB + col) = __floats2half2_rn(v2, v3);
            }
        } else {
            const float* be = bias + (size_t)e * DDIM;
            const int tokA = g_perm[rA];
            const int tokB = g_perm[rB];
#pragma unroll
            for (int nj = 0; nj < 8; nj++) {
                const int col = nt * 128 + wn * 64 + nj * 8 + t4 * 2;
                float b0 = be[col], b1 = be[col + 1];
                if (tokA >= 0) {
                    float2 v = { c[mi][nj][0] + b0, c[mi][nj][1] + b1 };
                    *reinterpret_cast<float2*>(outp + (size_t)tokA * DDIM + col) = v;
                }
                if (tokB >= 0) {
                    float2 v = { c[mi][nj][2] + b0, c[mi][nj][3] + b1 };
                    *reinterpret_cast<float2*>(outp + (size_t)tokB * DDIM + col) = v;
                }
            }
        }
    }
}

// ---------------------------------------------------------------------------
// Launch: convert W1 -> GEMM1 -> convert W2 (overwrite) -> GEMM2
// ---------------------------------------------------------------------------
extern "C" void kernel_launch(void* const* d_in, const int* in_sizes, int n_in,
                              void* d_out, int out_size) {
    const float* x  = (const float*)d_in[0];
    const float* gW = (const float*)d_in[1];
    const float* gb = (const float*)d_in[2];
    const float* W1 = (const float*)d_in[3];
    const float* b1 = (const float*)d_in[4];
    const float* W2 = (const float*)d_in[5];
    const float* b2 = (const float*)d_in[6];
    float* out = (float*)d_out;

    static bool attr_done = false;
    if (!attr_done) {
        cudaFuncSetAttribute(moe_gemm_kernel<DDIM, true>,
                             cudaFuncAttributeMaxDynamicSharedMemorySize, GEMM_SMEM);
        cudaFuncSetAttribute(moe_gemm_kernel<DFF, false>,
                             cudaFuncAttributeMaxDynamicSharedMemorySize, GEMM_SMEM);
        attr_done = true;
    }

    init_kernel<<<NPAD / 256, 256>>>();
    gate_kernel<<<NTOK / 8, 256>>>(x, gW, gb);
    scan_kernel<<<1, 1>>>();
    gather_kernel<<<NTOK / 8, 256>>>(x);

    transpose_cvt_W1<<<dim3(DFF / 32, DDIM / 64, NEXP), dim3(32, 8)>>>(W1);
    moe_gemm_kernel<DDIM, true ><<<dim3(MTMAX, DFF / 128), 256, GEMM_SMEM>>>(b1, nullptr);

    transpose_cvt_W2<<<dim3(DDIM / 32, DFF / 64, NEXP), dim3(32, 8)>>>(W2);
    moe_gemm_kernel<DFF,  false><<<dim3(MTMAX, DDIM / 128), 256, GEMM_SMEM>>>(b2, out);
}

// round 13
// speedup vs baseline: 1.1280x; 1.0641x over previous
#include <cuda_runtime.h>
#include <cuda_fp16.h>
#include <cstdint>
#include <math.h>

// Problem constants
#define NTOK 8192
#define DDIM 1024
#define DFF  4096
#define NEXP 8
#define NPAD 9216      // 8192 + 8*128 headroom, multiple of 128
#define MTMAX 72       // max total M-tiles across experts (9216/128)

// ---------------------------------------------------------------------------
// Scratch (device globals; no dynamic allocation allowed)
// g_Wh shared by both GEMMs (stream-ordered overwrite between phases).
// ---------------------------------------------------------------------------
__device__ int    g_expert_id[NTOK];
__device__ int    g_cursor[NEXP];
__device__ int    g_tile_off[NEXP + 1];
__device__ int    g_perm[NPAD];
__device__ __half g_xh[(size_t)NPAD * DDIM];          // permuted tokens, fp16
__device__ __half g_h[(size_t)NPAD * DFF];            // hidden activations, fp16
__device__ __half g_Wh[(size_t)NEXP * DFF * DDIM];    // W1^T then W2^T, K-major

// ---------------------------------------------------------------------------
// helpers
// ---------------------------------------------------------------------------
__device__ __forceinline__ uint32_t smem_u32(const void* p) {
    uint32_t a;
    asm("{ .reg .u64 t; cvta.to.shared.u64 t, %1; cvt.u32.u64 %0, t; }"
        : "=r"(a) : "l"(p));
    return a;
}

__device__ __forceinline__ void ldsm4(uint32_t* r, uint32_t addr) {
    asm volatile("ldmatrix.sync.aligned.m8n8.x4.shared.b16 {%0,%1,%2,%3}, [%4];"
                 : "=r"(r[0]), "=r"(r[1]), "=r"(r[2]), "=r"(r[3]) : "r"(addr));
}

__device__ __forceinline__ void mma16816(float* c, const uint32_t* a,
                                         uint32_t b0, uint32_t b1) {
    asm volatile(
        "mma.sync.aligned.m16n8k16.row.col.f32.f16.f16.f32 "
        "{%0,%1,%2,%3},{%4,%5,%6,%7},{%8,%9},{%0,%1,%2,%3};"
        : "+f"(c[0]), "+f"(c[1]), "+f"(c[2]), "+f"(c[3])
        : "r"(a[0]), "r"(a[1]), "r"(a[2]), "r"(a[3]), "r"(b0), "r"(b1));
}

__device__ __forceinline__ void cp16(uint32_t saddr, const void* g) {
    asm volatile("cp.async.cg.shared.global [%0], [%1], 16;"
                 :: "r"(saddr), "l"(g) : "memory");
}
#define CP_COMMIT() asm volatile("cp.async.commit_group;" ::: "memory")
#define CP_WAIT1()  asm volatile("cp.async.wait_group 1;" ::: "memory")

// ---------------------------------------------------------------------------
// transpose-convert body: fp32 [rows][cols] -> fp16 transposed [cols][rows]
// 1D 256-thread block; 64(r) x 32(c) tile per block.
// ---------------------------------------------------------------------------
__device__ __forceinline__ void transpose_cvt_tile(const float* __restrict__ in,
                                                   __half* __restrict__ out,
                                                   int rows, int cols,
                                                   int bx, int by, int bz,
                                                   int tid, float* tilebuf) {
    // tilebuf layout: [32][66] floats ([c][r], 64 r + 2 pad)
    size_t mat = (size_t)rows * cols;
    in  += (size_t)bz * mat;
    out += (size_t)bz * mat;
    int c0 = bx * 32, r0 = by * 64;
    int tx = tid & 31, ty = tid >> 5;          // 32 x 8
#pragma unroll
    for (int i = 0; i < 64; i += 8)
        tilebuf[tx * 66 + ty + i] = in[(size_t)(r0 + ty + i) * cols + (c0 + tx)];
    __syncthreads();
#pragma unroll
    for (int i = 0; i < 32; i += 8) {
        int c = ty + i;
        float v0 = tilebuf[c * 66 + tx * 2];
        float v1 = tilebuf[c * 66 + tx * 2 + 1];
        *reinterpret_cast<__half2*>(out + (size_t)(c0 + c) * rows + (r0 + tx * 2)) =
            __floats2half2_rn(v0, v1);
    }
}

// ---------------------------------------------------------------------------
// 1) fused gate + W1 transpose-convert (independent roles, one launch)
//    blocks [0, 1024)            : gating (warp per token, fp32, strict argmax)
//    blocks [1024, 1024+16384)   : W1 [D][DFF] -> g_Wh [DFF][D] fp16
// ---------------------------------------------------------------------------
#define GATE_BLKS 1024
#define CVT1_BLKS (128 * 16 * 8)   // (DFF/32) x (DDIM/64) x NEXP

__global__ __launch_bounds__(256)
void gate_cvt1_kernel(const float* __restrict__ x,
                      const float* __restrict__ gW,
                      const float* __restrict__ gb,
                      const float* __restrict__ W1) {
    __shared__ float tilebuf[32 * 66];
    const int bid = blockIdx.x;
    const int tid = threadIdx.x;

    if (bid >= GATE_BLKS) {
        int c = bid - GATE_BLKS;
        int bx = c & 127;            // DFF/32
        int by = (c >> 7) & 15;      // DDIM/64
        int bz = c >> 11;            // expert
        transpose_cvt_tile(W1, g_Wh, DDIM, DFF, bx, by, bz, tid, tilebuf);
        return;
    }

    int tok  = bid * 8 + (tid >> 5);
    int lane = tid & 31;
    const float* xr = x + (size_t)tok * DDIM;
    float acc[8];
#pragma unroll
    for (int j = 0; j < 8; j++) acc[j] = 0.f;
#pragma unroll 8
    for (int i = 0; i < 32; i++) {
        int d = lane + i * 32;
        float xv = xr[d];
        float4 w0 = *reinterpret_cast<const float4*>(gW + (size_t)d * 8);
        float4 w1 = *reinterpret_cast<const float4*>(gW + (size_t)d * 8 + 4);
        acc[0] += xv * w0.x; acc[1] += xv * w0.y; acc[2] += xv * w0.z; acc[3] += xv * w0.w;
        acc[4] += xv * w1.x; acc[5] += xv * w1.y; acc[6] += xv * w1.z; acc[7] += xv * w1.w;
    }
#pragma unroll
    for (int j = 0; j < 8; j++) {
#pragma unroll
        for (int o = 16; o; o >>= 1) acc[j] += __shfl_xor_sync(0xffffffffu, acc[j], o);
    }
    if (lane == 0) {
        float best = acc[0] + gb[0];
        int bi = 0;
#pragma unroll
        for (int j = 1; j < 8; j++) {
            float v = acc[j] + gb[j];
            if (v > best) { best = v; bi = j; }   // strict > : first-max, matches argmax
        }
        g_expert_id[tok] = bi;
    }
}

// ---------------------------------------------------------------------------
// 2) scan: histogram (smem) + padded prefix + tile table + perm init
// ---------------------------------------------------------------------------
__global__ __launch_bounds__(256) void scan_kernel() {
    __shared__ int hist[NEXP];
    int tid = threadIdx.x;
    if (tid < NEXP) hist[tid] = 0;
    __syncthreads();
    for (int i = tid; i < NTOK; i += 256)
        atomicAdd(&hist[g_expert_id[i]], 1);
    __syncthreads();
    if (tid == 0) {
        int off = 0, toff = 0;
        for (int e = 0; e < NEXP; e++) {
            int pad = (hist[e] + 127) & ~127;
            g_cursor[e]   = off;
            g_tile_off[e] = toff;
            off  += pad;
            toff += pad >> 7;
        }
        g_tile_off[NEXP] = toff;
    }
    for (int i = tid; i < NPAD; i += 256) g_perm[i] = -1;
}

// ---------------------------------------------------------------------------
// 3) gather: warp per token — permute + fp32->fp16
// ---------------------------------------------------------------------------
__global__ __launch_bounds__(256) void gather_kernel(const float* __restrict__ x) {
    int tok  = (blockIdx.x * 256 + threadIdx.x) >> 5;
    int lane = threadIdx.x & 31;
    if (tok >= NTOK) return;
    int e = g_expert_id[tok];
    int slot = 0;
    if (lane == 0) slot = atomicAdd(&g_cursor[e], 1);
    slot = __shfl_sync(0xffffffffu, slot, 0);
    if (lane == 0) g_perm[slot] = tok;
    const float4* xr = reinterpret_cast<const float4*>(x + (size_t)tok * DDIM);
    __half* dst = g_xh + (size_t)slot * DDIM;
#pragma unroll
    for (int i = 0; i < 8; i++) {
        float4 v = xr[lane + i * 32];
        __half hv[4] = { __float2half_rn(v.x), __float2half_rn(v.y),
                         __float2half_rn(v.z), __float2half_rn(v.w) };
        *reinterpret_cast<uint2*>(dst + lane * 4 + i * 128) =
            *reinterpret_cast<const uint2*>(hv);
    }
}

// ---------------------------------------------------------------------------
// 4) W2 transpose-convert (standalone; union buffer forces serial placement)
// ---------------------------------------------------------------------------
__global__ __launch_bounds__(256) void transpose_cvt_W2(const float* __restrict__ in) {
    __shared__ float tilebuf[32 * 66];
    transpose_cvt_tile(in, g_Wh, DFF, DDIM,
                       blockIdx.x, blockIdx.y, blockIdx.z, threadIdx.x, tilebuf);
}

// ---------------------------------------------------------------------------
// 5/6) mma.sync GEMM (exact R5 winner): 128x128 CTA tile, warp tile 32x64,
//      K-chunk 32, 2-stage cp.async, 80B smem rows (ldmatrix conflict-free)
//   PH1: h = gelu(xh @ W1h^T + b1)  -> fp16
//   PH2: out[perm] = h @ W2h^T + b2 -> fp32 scatter
// ---------------------------------------------------------------------------
static constexpr int ROWB   = 80;            // 64B data + 16B pad
static constexpr int TILEB  = 128 * ROWB;    // 10240 B per operand tile
static constexpr int STAGEB = 2 * TILEB;     // A + B per stage

template <int KDIM, bool PH1>
__global__ __launch_bounds__(256, 2)
void moe_gemm_kernel(const float* __restrict__ bias, float* __restrict__ outp) {
    __shared__ __align__(128) uint8_t smem[2 * STAGEB];   // 40 KB

    const int mt = blockIdx.x;
    if (mt >= g_tile_off[NEXP]) return;
    int e = 0;
#pragma unroll
    for (int i = 1; i < NEXP; i++)
        if (g_tile_off[i] <= mt) e = i;

    const int nt   = blockIdx.y;
    const int row0 = mt * 128;
    const int tid  = threadIdx.x;
    const int wid  = tid >> 5;
    const int lane = tid & 31;
    const int wm   = wid & 3;      // warp M index (4)
    const int wn   = wid >> 2;     // warp N index (2)
    const uint32_t sbase = smem_u32(smem);

    const __half* Ab = (PH1 ? g_xh : g_h) + (size_t)row0 * KDIM;
    const __half* Bb = g_Wh
                       + (size_t)e * (size_t)(PH1 ? DFF : DDIM) * KDIM
                       + (size_t)nt * 128 * KDIM;

    // per-thread load slots: 2 x (A 16B + B 16B) per chunk
    const int lr0 = tid >> 2,           lc0 = tid & 3;
    const int lr1 = (tid + 256) >> 2,   lc1 = (tid + 256) & 3;

    auto load_chunk = [&](int kc, int stage) {
        uint32_t sa = sbase + stage * STAGEB;
        uint32_t sb = sa + TILEB;
        cp16(sa + lr0 * ROWB + lc0 * 16, Ab + (size_t)lr0 * KDIM + kc * 32 + lc0 * 8);
        cp16(sb + lr0 * ROWB + lc0 * 16, Bb + (size_t)lr0 * KDIM + kc * 32 + lc0 * 8);
        cp16(sa + lr1 * ROWB + lc1 * 16, Ab + (size_t)lr1 * KDIM + kc * 32 + lc1 * 8);
        cp16(sb + lr1 * ROWB + lc1 * 16, Bb + (size_t)lr1 * KDIM + kc * 32 + lc1 * 8);
    };

    float c[2][8][4];
#pragma unroll
    for (int mi = 0; mi < 2; mi++)
#pragma unroll
        for (int nj = 0; nj < 8; nj++)
#pragma unroll
            for (int q = 0; q < 4; q++) c[mi][nj][q] = 0.f;

    const int lrow  = lane & 15;
    const int lhalf = (lane >> 4) & 1;
    constexpr int NK = KDIM / 32;

    load_chunk(0, 0);
    CP_COMMIT();

    for (int kc = 0; kc < NK; kc++) {
        int nk = (kc + 1 < NK) ? kc + 1 : kc;      // last iter: harmless reload
        load_chunk(nk, (kc + 1) & 1);
        CP_COMMIT();
        CP_WAIT1();
        __syncthreads();

        uint32_t As = sbase + (kc & 1) * STAGEB;
        uint32_t Bs = As + TILEB;
#pragma unroll
        for (int ks = 0; ks < 2; ks++) {
            const int bytecol = ks * 32 + lhalf * 16;
            uint32_t a[2][4], b[4][4];
#pragma unroll
            for (int mi = 0; mi < 2; mi++)
                ldsm4(a[mi], As + (wm * 32 + mi * 16 + lrow) * ROWB + bytecol);
#pragma unroll
            for (int nb = 0; nb < 4; nb++)
                ldsm4(b[nb], Bs + (wn * 64 + nb * 16 + lrow) * ROWB + bytecol);
#pragma unroll
            for (int mi = 0; mi < 2; mi++)
#pragma unroll
                for (int nb = 0; nb < 4; nb++) {
                    mma16816(c[mi][2 * nb + 0], a[mi], b[nb][0], b[nb][2]);
                    mma16816(c[mi][2 * nb + 1], a[mi], b[nb][1], b[nb][3]);
                }
        }
        __syncthreads();
    }

    // -------- epilogue from register accumulators --------
    const int g4 = lane >> 2, t4 = lane & 3;
#pragma unroll
    for (int mi = 0; mi < 2; mi++) {
        const int rA = row0 + wm * 32 + mi * 16 + g4;     // rows for c0,c1
        const int rB = rA + 8;                            // rows for c2,c3
        if constexpr (PH1) {
            const float* be = bias + (size_t)e * DFF;
            __half* hA = g_h + (size_t)rA * DFF;
            __half* hB = g_h + (size_t)rB * DFF;
#pragma unroll
            for (int nj = 0; nj < 8; nj++) {
                const int col = nt * 128 + wn * 64 + nj * 8 + t4 * 2;
                float b0 = be[col], b1 = be[col + 1];
                float v0 = c[mi][nj][0] + b0;
                float v1 = c[mi][nj][1] + b1;
                float v2 = c[mi][nj][2] + b0;
                float v3 = c[mi][nj][3] + b1;
                v0 = 0.5f * v0 * (1.0f + erff(v0 * 0.70710678118654752440f));
                v1 = 0.5f * v1 * (1.0f + erff(v1 * 0.70710678118654752440f));
                v2 = 0.5f * v2 * (1.0f + erff(v2 * 0.70710678118654752440f));
                v3 = 0.5f * v3 * (1.0f + erff(v3 * 0.70710678118654752440f));
                *reinterpret_cast<__half2*>(hA + col) = __floats2half2_rn(v0, v1);
                *reinterpret_cast<__half2*>(hB + col) = __floats2half2_rn(v2, v3);
            }
        } else {
            const float* be = bias + (size_t)e * DDIM;
            const int tokA = g_perm[rA];
            const int tokB = g_perm[rB];
#pragma unroll
            for (int nj = 0; nj < 8; nj++) {
                const int col = nt * 128 + wn * 64 + nj * 8 + t4 * 2;
                float b0 = be[col], b1 = be[col + 1];
                if (tokA >= 0) {
                    float2 v = { c[mi][nj][0] + b0, c[mi][nj][1] + b1 };
                    *reinterpret_cast<float2*>(outp + (size_t)tokA * DDIM + col) = v;
                }
                if (tokB >= 0) {
                    float2 v = { c[mi][nj][2] + b0, c[mi][nj][3] + b1 };
                    *reinterpret_cast<float2*>(outp + (size_t)tokB * DDIM + col) = v;
                }
            }
        }
    }
}

// ---------------------------------------------------------------------------
// Launch: [gate || cvtW1] -> scan -> gather -> GEMM1 -> cvtW2 -> GEMM2
// ---------------------------------------------------------------------------
extern "C" void kernel_launch(void* const* d_in, const int* in_sizes, int n_in,
                              void* d_out, int out_size) {
    const float* x  = (const float*)d_in[0];
    const float* gW = (const float*)d_in[1];
    const float* gb = (const float*)d_in[2];
    const float* W1 = (const float*)d_in[3];
    const float* b1 = (const float*)d_in[4];
    const float* W2 = (const float*)d_in[5];
    const float* b2 = (const float*)d_in[6];
    float* out = (float*)d_out;

    gate_cvt1_kernel<<<GATE_BLKS + CVT1_BLKS, 256>>>(x, gW, gb, W1);
    scan_kernel<<<1, 256>>>();
    gather_kernel<<<NTOK / 8, 256>>>(x);

    moe_gemm_kernel<DDIM, true ><<<dim3(MTMAX, DFF / 128), 256>>>(b1, nullptr);

    transpose_cvt_W2<<<dim3(DDIM / 32, DFF / 64, NEXP), 256>>>(W2);
    moe_gemm_kernel<DFF,  false><<<dim3(MTMAX, DDIM / 128), 256>>>(b2, out);
}

// round 15
// speedup vs baseline: 1.1783x; 1.0446x over previous
#include <cuda_runtime.h>
#include <cuda_fp16.h>
#include <cstdint>
#include <math.h>

// Problem constants
#define NTOK 8192
#define DDIM 1024
#define DFF  4096
#define NEXP 8
#define NPAD 9216      // 8192 + 8*128 headroom, multiple of 128
#define MTMAX 72       // max total M-tiles across experts (9216/128)

// ---------------------------------------------------------------------------
// Scratch (device globals; no dynamic allocation allowed)
// g_Wh shared by both GEMMs (stream-ordered overwrite between phases).
// ---------------------------------------------------------------------------
__device__ int    g_expert_id[NTOK];
__device__ int    g_cursor[NEXP];
__device__ int    g_tile_off[NEXP + 1];
__device__ int    g_perm[NPAD];
__device__ __half g_xh[(size_t)NPAD * DDIM];          // permuted tokens, fp16
__device__ __half g_h[(size_t)NPAD * DFF];            // hidden activations, fp16
__device__ __half g_Wh[(size_t)NEXP * DFF * DDIM];    // W1^T then W2^T, K-major

// ---------------------------------------------------------------------------
// helpers
// ---------------------------------------------------------------------------
__device__ __forceinline__ uint32_t smem_u32(const void* p) {
    uint32_t a;
    asm("{ .reg .u64 t; cvta.to.shared.u64 t, %1; cvt.u32.u64 %0, t; }"
        : "=r"(a) : "l"(p));
    return a;
}

__device__ __forceinline__ void ldsm4(uint32_t* r, uint32_t addr) {
    asm volatile("ldmatrix.sync.aligned.m8n8.x4.shared.b16 {%0,%1,%2,%3}, [%4];"
                 : "=r"(r[0]), "=r"(r[1]), "=r"(r[2]), "=r"(r[3]) : "r"(addr));
}

__device__ __forceinline__ void mma16816(float* c, const uint32_t* a,
                                         uint32_t b0, uint32_t b1) {
    asm volatile(
        "mma.sync.aligned.m16n8k16.row.col.f32.f16.f16.f32 "
        "{%0,%1,%2,%3},{%4,%5,%6,%7},{%8,%9},{%0,%1,%2,%3};"
        : "+f"(c[0]), "+f"(c[1]), "+f"(c[2]), "+f"(c[3])
        : "r"(a[0]), "r"(a[1]), "r"(a[2]), "r"(a[3]), "r"(b0), "r"(b1));
}

__device__ __forceinline__ void cp16(uint32_t saddr, const void* g) {
    asm volatile("cp.async.cg.shared.global [%0], [%1], 16;"
                 :: "r"(saddr), "l"(g) : "memory");
}
#define CP_COMMIT() asm volatile("cp.async.commit_group;" ::: "memory")
#define CP_WAIT1()  asm volatile("cp.async.wait_group 1;" ::: "memory")

// ---------------------------------------------------------------------------
// transpose-convert body: fp32 [rows][cols] -> fp16 transposed [cols][rows]
// 1D 256-thread block; 64(r) x 32(c) tile per block.
// ---------------------------------------------------------------------------
__device__ __forceinline__ void transpose_cvt_tile(const float* __restrict__ in,
                                                   __half* __restrict__ out,
                                                   int rows, int cols,
                                                   int bx, int by, int bz,
                                                   int tid, float* tilebuf) {
    // tilebuf layout: [32][66] floats ([c][r], 64 r + 2 pad)
    size_t mat = (size_t)rows * cols;
    in  += (size_t)bz * mat;
    out += (size_t)bz * mat;
    int c0 = bx * 32, r0 = by * 64;
    int tx = tid & 31, ty = tid >> 5;          // 32 x 8
#pragma unroll
    for (int i = 0; i < 64; i += 8)
        tilebuf[tx * 66 + ty + i] = in[(size_t)(r0 + ty + i) * cols + (c0 + tx)];
    __syncthreads();
#pragma unroll
    for (int i = 0; i < 32; i += 8) {
        int c = ty + i;
        float v0 = tilebuf[c * 66 + tx * 2];
        float v1 = tilebuf[c * 66 + tx * 2 + 1];
        *reinterpret_cast<__half2*>(out + (size_t)(c0 + c) * rows + (r0 + tx * 2)) =
            __floats2half2_rn(v0, v1);
    }
}

// ---------------------------------------------------------------------------
// 1) fused gate + W1 transpose-convert (independent roles, one launch)
// ---------------------------------------------------------------------------
#define GATE_BLKS 1024
#define CVT1_BLKS (128 * 16 * 8)   // (DFF/32) x (DDIM/64) x NEXP

__global__ __launch_bounds__(256)
void gate_cvt1_kernel(const float* __restrict__ x,
                      const float* __restrict__ gW,
                      const float* __restrict__ gb,
                      const float* __restrict__ W1) {
    __shared__ float tilebuf[32 * 66];
    const int bid = blockIdx.x;
    const int tid = threadIdx.x;

    if (bid >= GATE_BLKS) {
        int c = bid - GATE_BLKS;
        int bx = c & 127;            // DFF/32
        int by = (c >> 7) & 15;      // DDIM/64
        int bz = c >> 11;            // expert
        transpose_cvt_tile(W1, g_Wh, DDIM, DFF, bx, by, bz, tid, tilebuf);
        return;
    }

    int tok  = bid * 8 + (tid >> 5);
    int lane = tid & 31;
    const float* xr = x + (size_t)tok * DDIM;
    float acc[8];
#pragma unroll
    for (int j = 0; j < 8; j++) acc[j] = 0.f;
#pragma unroll 8
    for (int i = 0; i < 32; i++) {
        int d = lane + i * 32;
        float xv = xr[d];
        float4 w0 = *reinterpret_cast<const float4*>(gW + (size_t)d * 8);
        float4 w1 = *reinterpret_cast<const float4*>(gW + (size_t)d * 8 + 4);
        acc[0] += xv * w0.x; acc[1] += xv * w0.y; acc[2] += xv * w0.z; acc[3] += xv * w0.w;
        acc[4] += xv * w1.x; acc[5] += xv * w1.y; acc[6] += xv * w1.z; acc[7] += xv * w1.w;
    }
#pragma unroll
    for (int j = 0; j < 8; j++) {
#pragma unroll
        for (int o = 16; o; o >>= 1) acc[j] += __shfl_xor_sync(0xffffffffu, acc[j], o);
    }
    if (lane == 0) {
        float best = acc[0] + gb[0];
        int bi = 0;
#pragma unroll
        for (int j = 1; j < 8; j++) {
            float v = acc[j] + gb[j];
            if (v > best) { best = v; bi = j; }   // strict > : first-max, matches argmax
        }
        g_expert_id[tok] = bi;
    }
}

// ---------------------------------------------------------------------------
// 2) scan: histogram (smem) + padded prefix + tile table + perm init
// ---------------------------------------------------------------------------
__global__ __launch_bounds__(256) void scan_kernel() {
    __shared__ int hist[NEXP];
    int tid = threadIdx.x;
    if (tid < NEXP) hist[tid] = 0;
    __syncthreads();
    for (int i = tid; i < NTOK; i += 256)
        atomicAdd(&hist[g_expert_id[i]], 1);
    __syncthreads();
    if (tid == 0) {
        int off = 0, toff = 0;
        for (int e = 0; e < NEXP; e++) {
            int pad = (hist[e] + 127) & ~127;
            g_cursor[e]   = off;
            g_tile_off[e] = toff;
            off  += pad;
            toff += pad >> 7;
        }
        g_tile_off[NEXP] = toff;
    }
    for (int i = tid; i < NPAD; i += 256) g_perm[i] = -1;
}

// ---------------------------------------------------------------------------
// 3) gather: warp per token — permute + fp32->fp16
// ---------------------------------------------------------------------------
__global__ __launch_bounds__(256) void gather_kernel(const float* __restrict__ x) {
    int tok  = (blockIdx.x * 256 + threadIdx.x) >> 5;
    int lane = threadIdx.x & 31;
    if (tok >= NTOK) return;
    int e = g_expert_id[tok];
    int slot = 0;
    if (lane == 0) slot = atomicAdd(&g_cursor[e], 1);
    slot = __shfl_sync(0xffffffffu, slot, 0);
    if (lane == 0) g_perm[slot] = tok;
    const float4* xr = reinterpret_cast<const float4*>(x + (size_t)tok * DDIM);
    __half* dst = g_xh + (size_t)slot * DDIM;
#pragma unroll
    for (int i = 0; i < 8; i++) {
        float4 v = xr[lane + i * 32];
        __half hv[4] = { __float2half_rn(v.x), __float2half_rn(v.y),
                         __float2half_rn(v.z), __float2half_rn(v.w) };
        *reinterpret_cast<uint2*>(dst + lane * 4 + i * 128) =
            *reinterpret_cast<const uint2*>(hv);
    }
}

// ---------------------------------------------------------------------------
// 4) W2 transpose-convert (standalone; union buffer forces serial placement)
// ---------------------------------------------------------------------------
__global__ __launch_bounds__(256) void transpose_cvt_W2(const float* __restrict__ in) {
    __shared__ float tilebuf[32 * 66];
    transpose_cvt_tile(in, g_Wh, DFF, DDIM,
                       blockIdx.x, blockIdx.y, blockIdx.z, threadIdx.x, tilebuf);
}

// ---------------------------------------------------------------------------
// 5/6) mma.sync GEMM: 128x128 CTA tile, warp tile 32x64, K-chunk 64,
//      2-stage cp.async, 144B smem rows (128B data + 16B pad; ldmatrix
//      conflict-free: row bases mod 128 step by 16)
//   PH1: h = gelu(xh @ W1h^T + b1)  -> fp16
//   PH2: out[perm] = h @ W2h^T + b2 -> fp32 scatter
// ---------------------------------------------------------------------------
static constexpr int ROWB   = 144;           // 128B data + 16B pad
static constexpr int TILEB  = 128 * ROWB;    // 18432 B per operand tile
static constexpr int STAGEB = 2 * TILEB;     // A + B per stage = 36864
static constexpr int GEMM_SMEM = 2 * STAGEB; // 73728 (dynamic)

template <int KDIM, bool PH1>
__global__ __launch_bounds__(256, 2)
void moe_gemm_kernel(const float* __restrict__ bias, float* __restrict__ outp) {
    extern __shared__ __align__(128) uint8_t smem[];

    const int mt = blockIdx.x;
    if (mt >= g_tile_off[NEXP]) return;
    int e = 0;
#pragma unroll
    for (int i = 1; i < NEXP; i++)
        if (g_tile_off[i] <= mt) e = i;

    const int nt   = blockIdx.y;
    const int row0 = mt * 128;
    const int tid  = threadIdx.x;
    const int wid  = tid >> 5;
    const int lane = tid & 31;
    const int wm   = wid & 3;      // warp M index (4)
    const int wn   = wid >> 2;     // warp N index (2)
    const uint32_t sbase = smem_u32(smem);

    const __half* Ab = (PH1 ? g_xh : g_h) + (size_t)row0 * KDIM;
    const __half* Bb = g_Wh
                       + (size_t)e * (size_t)(PH1 ? DFF : DDIM) * KDIM
                       + (size_t)nt * 128 * KDIM;

    // per-thread load mapping: 4 j-slots x (A 16B + B 16B); i = tid + j*256,
    // row = i>>3, chunk-col = i&7. Hoisted base pointers; only kc*64 varies.
    const __half* aptr[4];
    const __half* bptr[4];
    uint32_t      soff[4];
#pragma unroll
    for (int j = 0; j < 4; j++) {
        int i = tid + j * 256;
        int r = i >> 3, cc = i & 7;
        aptr[j] = Ab + (size_t)r * KDIM + cc * 8;
        bptr[j] = Bb + (size_t)r * KDIM + cc * 8;
        soff[j] = r * ROWB + cc * 16;
    }

    auto load_chunk = [&](int kc, int stage) {
        uint32_t sa = sbase + stage * STAGEB;
        uint32_t sb = sa + TILEB;
        int ko = kc * 64;
#pragma unroll
        for (int j = 0; j < 4; j++) {
            cp16(sa + soff[j], aptr[j] + ko);
            cp16(sb + soff[j], bptr[j] + ko);
        }
    };

    float c[2][8][4];
#pragma unroll
    for (int mi = 0; mi < 2; mi++)
#pragma unroll
        for (int nj = 0; nj < 8; nj++)
#pragma unroll
            for (int q = 0; q < 4; q++) c[mi][nj][q] = 0.f;

    const int lrow  = lane & 15;
    const int lhalf = (lane >> 4) & 1;
    // hoisted ldsm row offsets (stage/bytecol added per use)
    const uint32_t aoff0 = (wm * 32 + lrow) * ROWB + lhalf * 16;
    const uint32_t aoff1 = aoff0 + 16 * ROWB;
    uint32_t boff[4];
#pragma unroll
    for (int nb = 0; nb < 4; nb++)
        boff[nb] = (wn * 64 + nb * 16 + lrow) * ROWB + lhalf * 16;

    constexpr int NK = KDIM / 64;

    load_chunk(0, 0);
    CP_COMMIT();

    for (int kc = 0; kc < NK; kc++) {
        int nk = (kc + 1 < NK) ? kc + 1 : kc;      // last iter: harmless reload
        load_chunk(nk, (kc + 1) & 1);
        CP_COMMIT();
        CP_WAIT1();
        __syncthreads();

        uint32_t As = sbase + (kc & 1) * STAGEB;
        uint32_t Bs = As + TILEB;
#pragma unroll
        for (int ks = 0; ks < 4; ks++) {
            const uint32_t bytecol = ks * 32;
            uint32_t a[2][4], b[4][4];
            ldsm4(a[0], As + aoff0 + bytecol);
            ldsm4(a[1], As + aoff1 + bytecol);
#pragma unroll
            for (int nb = 0; nb < 4; nb++)
                ldsm4(b[nb], Bs + boff[nb] + bytecol);
#pragma unroll
            for (int mi = 0; mi < 2; mi++)
#pragma unroll
                for (int nb = 0; nb < 4; nb++) {
                    mma16816(c[mi][2 * nb + 0], a[mi], b[nb][0], b[nb][2]);
                    mma16816(c[mi][2 * nb + 1], a[mi], b[nb][1], b[nb][3]);
                }
        }
        __syncthreads();
    }

    // -------- epilogue from register accumulators --------
    const int g4 = lane >> 2, t4 = lane & 3;
#pragma unroll
    for (int mi = 0; mi < 2; mi++) {
        const int rA = row0 + wm * 32 + mi * 16 + g4;     // rows for c0,c1
        const int rB = rA + 8;                            // rows for c2,c3
        if constexpr (PH1) {
            const float* be = bias + (size_t)e * DFF;
            __half* hA = g_h + (size_t)rA * DFF;
            __half* hB = g_h + (size_t)rB * DFF;
#pragma unroll
            for (int nj = 0; nj < 8; nj++) {
                const int col = nt * 128 + wn * 64 + nj * 8 + t4 * 2;
                float b0 = be[col], b1 = be[col + 1];
                float v0 = c[mi][nj][0] + b0;
                float v1 = c[mi][nj][1] + b1;
                float v2 = c[mi][nj][2] + b0;
                float v3 = c[mi][nj][3] + b1;
                v0 = 0.5f * v0 * (1.0f + erff(v0 * 0.70710678118654752440f));
                v1 = 0.5f * v1 * (1.0f + erff(v1 * 0.70710678118654752440f));
                v2 = 0.5f * v2 * (1.0f + erff(v2 * 0.70710678118654752440f));
                v3 = 0.5f * v3 * (1.0f + erff(v3 * 0.70710678118654752440f));
                *reinterpret_cast<__half2*>(hA + col) = __floats2half2_rn(v0, v1);
                *reinterpret_cast<__half2*>(hB + col) = __floats2half2_rn(v2, v3);
            }
        } else {
            const float* be = bias + (size_t)e * DDIM;
            const int tokA = g_perm[rA];
            const int tokB = g_perm[rB];
#pragma unroll
            for (int nj = 0; nj < 8; nj++) {
                const int col = nt * 128 + wn * 64 + nj * 8 + t4 * 2;
                float b0 = be[col], b1 = be[col + 1];
                if (tokA >= 0) {
                    float2 v = { c[mi][nj][0] + b0, c[mi][nj][1] + b1 };
                    *reinterpret_cast<float2*>(outp + (size_t)tokA * DDIM + col) = v;
                }
                if (tokB >= 0) {
                    float2 v = { c[mi][nj][2] + b0, c[mi][nj][3] + b1 };
                    *reinterpret_cast<float2*>(outp + (size_t)tokB * DDIM + col) = v;
                }
            }
        }
    }
}

// ---------------------------------------------------------------------------
// Launch: [gate || cvtW1] -> scan -> gather -> GEMM1 -> cvtW2 -> GEMM2
// ---------------------------------------------------------------------------
extern "C" void kernel_launch(void* const* d_in, const int* in_sizes, int n_in,
                              void* d_out, int out_size) {
    const float* x  = (const float*)d_in[0];
    const float* gW = (const float*)d_in[1];
    const float* gb = (const float*)d_in[2];
    const float* W1 = (const float*)d_in[3];
    const float* b1 = (const float*)d_in[4];
    const float* W2 = (const float*)d_in[5];
    const float* b2 = (const float*)d_in[6];
    float* out = (float*)d_out;

    static bool attr_done = false;
    if (!attr_done) {
        cudaFuncSetAttribute(moe_gemm_kernel<DDIM, true>,
                             cudaFuncAttributeMaxDynamicSharedMemorySize, GEMM_SMEM);
        cudaFuncSetAttribute(moe_gemm_kernel<DFF, false>,
                             cudaFuncAttributeMaxDynamicSharedMemorySize, GEMM_SMEM);
        attr_done = true;
    }

    gate_cvt1_kernel<<<GATE_BLKS + CVT1_BLKS, 256>>>(x, gW, gb, W1);
    scan_kernel<<<1, 256>>>();
    gather_kernel<<<NTOK / 8, 256>>>(x);

    moe_gemm_kernel<DDIM, true ><<<dim3(MTMAX, DFF / 128), 256, GEMM_SMEM>>>(b1, nullptr);

    transpose_cvt_W2<<<dim3(DDIM / 32, DFF / 64, NEXP), 256>>>(W2);
    moe_gemm_kernel<DFF,  false><<<dim3(MTMAX, DDIM / 128), 256, GEMM_SMEM>>>(b2, out);
}